// round 4
// baseline (speedup 1.0000x reference)
#include <cuda_runtime.h>
#include <math.h>

// ---------------- scratch (no allocation allowed) ----------------
#define NEL 16777216  // 16*64*128*128  == 16*256*64*64
__device__ float g_buf0[NEL];
__device__ float g_buf1[NEL];
__device__ float g_buf2[NEL];
__device__ float g_imap[262144];   // 16*128*128
__device__ float g_inc[262144];
__device__ float g_mean[256];
__device__ float g_rstd[256];

// ---------------- 3x3 conv, pad=1, 64x64 output tile, 4x4 per thread -------
// 256 threads; thread t = (tx = t&15, ty = t>>4) computes out rows ty*4..+3,
// cols tx*4..+3 of the tile. grid: (W/64, H/64, B*Cout)
template<int CIN>
__global__ void __launch_bounds__(256, 2)
conv3x3v2(const float* __restrict__ in, const float* __restrict__ wt,
          const float* __restrict__ bias, float* __restrict__ out,
          int Cout, int H, int W) {
    __shared__ float tile[66][68];     // rows 16B-aligned (68*4 = 272)
    __shared__ float wsm[CIN * 9];
    const int co = blockIdx.z % Cout;
    const int n  = blockIdx.z / Cout;
    const int tid = threadIdx.x;
    const int tx = tid & 15, ty = tid >> 4;
    for (int i = tid; i < CIN * 9; i += 256)
        wsm[i] = wt[(size_t)co * CIN * 9 + i];
    const int oy0 = blockIdx.y * 64;
    const int ox0 = blockIdx.x * 64;
    float acc[4][4] = {};
    const float* inb = in + (size_t)n * CIN * H * W;
    for (int ci = 0; ci < CIN; ci++) {
        __syncthreads();   // wsm ready (iter 0) / tile reuse safe (iter>0)
        const float* ip = inb + (size_t)ci * H * W;
        #pragma unroll
        for (int k = 0; k < 18; k++) {
            int i = tid + k * 256;
            if (i < 66 * 66) {
                int ly = i / 66, lx = i - ly * 66;
                int gy = oy0 + ly - 1, gx = ox0 + lx - 1;
                float v = 0.f;
                if (gy >= 0 && gy < H && gx >= 0 && gx < W) v = ip[(size_t)gy * W + gx];
                tile[ly][lx] = v;
            }
        }
        __syncthreads();
        float w[9];
        #pragma unroll
        for (int j = 0; j < 9; j++) w[j] = wsm[ci * 9 + j];
        #pragma unroll
        for (int iy = 0; iy < 6; iy++) {
            float4 va = *(const float4*)&tile[ty * 4 + iy][tx * 4];
            float2 vb = *(const float2*)&tile[ty * 4 + iy][tx * 4 + 4];
            float v0 = va.x, v1 = va.y, v2 = va.z, v3 = va.w, v4 = vb.x, v5 = vb.y;
            #pragma unroll
            for (int r = 0; r < 4; r++) {
                const int wr = iy - r;
                if (wr >= 0 && wr < 3) {
                    float w0 = w[wr * 3], w1 = w[wr * 3 + 1], w2 = w[wr * 3 + 2];
                    acc[r][0] = fmaf(v0, w0, fmaf(v1, w1, fmaf(v2, w2, acc[r][0])));
                    acc[r][1] = fmaf(v1, w0, fmaf(v2, w1, fmaf(v3, w2, acc[r][1])));
                    acc[r][2] = fmaf(v2, w0, fmaf(v3, w1, fmaf(v4, w2, acc[r][2])));
                    acc[r][3] = fmaf(v3, w0, fmaf(v4, w1, fmaf(v5, w2, acc[r][3])));
                }
            }
        }
    }
    float bv = bias[co];
    #pragma unroll
    for (int r = 0; r < 4; r++) {
        int oy = oy0 + ty * 4 + r;
        float4 o = make_float4(acc[r][0] + bv, acc[r][1] + bv, acc[r][2] + bv, acc[r][3] + bv);
        *(float4*)&out[(((size_t)n * Cout + co) * H + oy) * W + ox0 + tx * 4] = o;
    }
}

// ---------------- BN batch statistics (one block per channel) ----------------
__global__ void bn_stats_k(const float* __restrict__ x, int C, int HW, int Bn) {
    const int c = blockIdx.x;
    const int N = Bn * HW;
    float s = 0.f, s2 = 0.f;
    for (int i = threadIdx.x; i < N; i += blockDim.x) {
        int n = i / HW, j = i - n * HW;
        float v = x[((size_t)n * C + c) * HW + j];
        s += v; s2 += v * v;
    }
    __shared__ float sh[256], sh2[256];
    sh[threadIdx.x] = s; sh2[threadIdx.x] = s2;
    __syncthreads();
    for (int o = 128; o > 0; o >>= 1) {
        if (threadIdx.x < o) { sh[threadIdx.x] += sh[threadIdx.x + o]; sh2[threadIdx.x] += sh2[threadIdx.x + o]; }
        __syncthreads();
    }
    if (threadIdx.x == 0) {
        float m = sh[0] / (float)N;
        float var = sh2[0] / (float)N - m * m;
        g_mean[c] = m;
        g_rstd[c] = rsqrtf(var + 1e-5f);
    }
}

// ---------------- BN apply + ReLU + PixelShuffle(2) ----------------
__global__ void bn_relu_ps_k(const float* __restrict__ y, const float* __restrict__ g,
                             const float* __restrict__ be, float* __restrict__ dep) {
    int idx = blockIdx.x * 256 + threadIdx.x;   // 0 .. 16M
    int X = idx & 127;
    int Y = (idx >> 7) & 127;
    int c = (idx >> 14) & 63;
    int n = idx >> 20;
    int cy = c * 4 + (Y & 1) * 2 + (X & 1);
    float v = y[(((size_t)n * 256 + cy) * 64 + (Y >> 1)) * 64 + (X >> 1)];
    v = (v - g_mean[cy]) * g_rstd[cy] * g[cy] + be[cy];
    dep[idx] = fmaxf(v, 0.f);
}

// ---------------- BN apply + ReLU in-place ----------------
__global__ void bn_relu_k(float* __restrict__ x, const float* __restrict__ g,
                          const float* __restrict__ be) {
    int idx = blockIdx.x * 256 + threadIdx.x;
    int c = (idx >> 14) & 63;    // HW = 16384, C = 64
    float v = x[idx];
    v = (v - g_mean[c]) * g_rstd[c] * g[c] + be[c];
    x[idx] = fmaxf(v, 0.f);
}

// ---------------- bilinear x2 (align_corners) + sigmoid ----------------
__global__ void up_sig_k(const float* __restrict__ in) {
    int idx = blockIdx.x * 256 + threadIdx.x;   // 16*128*128
    int X = idx & 127, Y = (idx >> 7) & 127, n = idx >> 14;
    const float sc = 63.0f / 127.0f;
    float yy = Y * sc, xx = X * sc;
    int y0 = (int)floorf(yy); float wy = yy - (float)y0; int y1 = min(y0 + 1, 63);
    int x0 = (int)floorf(xx); float wx = xx - (float)x0; int x1 = min(x0 + 1, 63);
    const float* p = in + n * 4096;
    float r0 = p[y0 * 64 + x0] * (1.f - wx) + p[y0 * 64 + x1] * wx;
    float r1 = p[y1 * 64 + x0] * (1.f - wx) + p[y1 * 64 + x1] * wx;
    float v = r0 * (1.f - wy) + r1 * wy;
    g_imap[idx] = 1.f / (1.f + expf(-v));
}

// ---------------- increase_map = dilate3x3(imap) - imap ----------------
__global__ void inc_k() {
    int idx = blockIdx.x * 256 + threadIdx.x;   // 16*128*128
    int X = idx & 127, Y = (idx >> 7) & 127, n = idx >> 14;
    const float* p = g_imap + (n << 14);
    float m = -1e30f;
    #pragma unroll
    for (int dy = -1; dy <= 1; dy++) {
        int y = Y + dy;
        if (y < 0 || y > 127) continue;
        #pragma unroll
        for (int dx = -1; dx <= 1; dx++) {
            int x = X + dx;
            if (x < 0 || x > 127) continue;
            m = fmaxf(m, p[y * 128 + x]);
        }
    }
    g_inc[idx] = m - p[Y * 128 + X];
}

// ---------------- b_feature = cur_x * increase_map ----------------
__global__ void mult_k(const float* __restrict__ cur) {
    int idx = blockIdx.x * 256 + threadIdx.x;   // 16M
    int sp = idx & 16383;
    int n = idx >> 20;
    g_buf2[idx] = cur[idx] * g_inc[(n << 14) | sp];
}

// ---------------- t = dep + beta * fn ----------------
__global__ void add_k(const float* __restrict__ beta) {
    int idx = blockIdx.x * 256 + threadIdx.x;
    g_buf2[idx] = g_buf1[idx] + beta[0] * g_buf0[idx];
}

// ---------------- 7x7 conv, Cin=64 -> 1, pad=3 ----------------
__global__ void conv7x7_k(const float* __restrict__ in, const float* __restrict__ wt,
                          const float* __restrict__ bias, float* __restrict__ out) {
    __shared__ float tile[22][22];
    __shared__ float wsm[64 * 49];
    const int n = blockIdx.z;
    const int tid = threadIdx.y * 16 + threadIdx.x;
    for (int i = tid; i < 64 * 49; i += 256) wsm[i] = wt[i];
    const int oy0 = blockIdx.y * 16, ox0 = blockIdx.x * 16;
    float acc = 0.f;
    for (int ci = 0; ci < 64; ci++) {
        __syncthreads();
        const float* ip = in + ((size_t)n * 64 + ci) * 16384;
        for (int i = tid; i < 22 * 22; i += 256) {
            int ly = i / 22, lx = i % 22;
            int gy = oy0 + ly - 3, gx = ox0 + lx - 3;
            float v = 0.f;
            if (gy >= 0 && gy < 128 && gx >= 0 && gx < 128) v = ip[gy * 128 + gx];
            tile[ly][lx] = v;
        }
        __syncthreads();
        const float* wp = &wsm[ci * 49];
        #pragma unroll
        for (int dy = 0; dy < 7; dy++)
            #pragma unroll
            for (int dx = 0; dx < 7; dx++)
                acc = fmaf(tile[threadIdx.y + dy][threadIdx.x + dx], wp[dy * 7 + dx], acc);
    }
    out[((size_t)n * 128 + oy0 + threadIdx.y) * 128 + ox0 + threadIdx.x] = acc + bias[0];
}

// ---------------- launch ----------------
extern "C" void kernel_launch(void* const* d_in, const int* in_sizes, int n_in,
                              void* d_out, int out_size) {
    static float *buf0 = nullptr, *buf1 = nullptr, *buf2 = nullptr;
    if (!buf0) {
        cudaGetSymbolAddress((void**)&buf0, g_buf0);
        cudaGetSymbolAddress((void**)&buf1, g_buf1);
        cudaGetSymbolAddress((void**)&buf2, g_buf2);
    }
    const float* cur_x  = (const float*)d_in[0];
    const float* dep_x  = (const float*)d_in[1];
    const float* in_map = (const float*)d_in[2];
    const float* up_w   = (const float*)d_in[3];
    const float* up_b   = (const float*)d_in[4];
    const float* up_g   = (const float*)d_in[5];
    const float* up_be  = (const float*)d_in[6];
    const float* conv2_w = (const float*)d_in[7];
    const float* conv2_b = (const float*)d_in[8];
    const float* beta   = (const float*)d_in[9];
    const float* d1_w = (const float*)d_in[10], *d1_b = (const float*)d_in[11];
    const float* d1_g = (const float*)d_in[12], *d1_be = (const float*)d_in[13];
    const float* d2_w = (const float*)d_in[14], *d2_b = (const float*)d_in[15];
    const float* d2_g = (const float*)d_in[16], *d2_be = (const float*)d_in[17];
    const float* d3_w = (const float*)d_in[18], *d3_b = (const float*)d_in[19];
    const float* d3_g = (const float*)d_in[20], *d3_be = (const float*)d_in[21];
    const float* out_w = (const float*)d_in[22], *out_b = (const float*)d_in[23];

    float* r_out = (float*)d_out;               // [16,64,128,128]
    float* map_out = (float*)d_out + NEL;       // [16,1,128,128]

    dim3 gUp(1, 1, 16 * 256);     // H=W=64, one 64x64 tile, Cout=256
    dim3 gD(2, 2, 16 * 64);       // H=W=128, 64x64 tiles, Cout=64
    const int EW = NEL / 256;     // elementwise grid (65536)

    // up path: conv(C2->4C1) + BN + ReLU + pixel shuffle
    conv3x3v2<128><<<gUp, 256>>>(dep_x, up_w, up_b, buf0, 256, 64, 64);
    bn_stats_k<<<256, 256>>>(buf0, 256, 4096, 16);
    bn_relu_ps_k<<<EW, 256>>>(buf0, up_g, up_be, buf1);   // buf1 = dep

    // attention-map path
    up_sig_k<<<1024, 256>>>(in_map);
    inc_k<<<1024, 256>>>();
    mult_k<<<EW, 256>>>(cur_x);                            // buf2 = b_feature

    // fn = conv2(b_feature)
    conv3x3v2<64><<<gD, 256>>>(buf2, conv2_w, conv2_b, buf0, 64, 128, 128);  // buf0 = fn
    add_k<<<EW, 256>>>(beta);                              // buf2 = dep + beta*fn

    // d1
    conv3x3v2<64><<<gD, 256>>>(buf2, d1_w, d1_b, buf0, 64, 128, 128);
    bn_stats_k<<<64, 256>>>(buf0, 64, 16384, 16);
    bn_relu_k<<<EW, 256>>>(buf0, d1_g, d1_be);
    // d2
    conv3x3v2<64><<<gD, 256>>>(buf0, d2_w, d2_b, buf1, 64, 128, 128);
    bn_stats_k<<<64, 256>>>(buf1, 64, 16384, 16);
    bn_relu_k<<<EW, 256>>>(buf1, d2_g, d2_be);
    // d3 -> r (first output region)
    conv3x3v2<64><<<gD, 256>>>(buf1, d3_w, d3_b, r_out, 64, 128, 128);
    bn_stats_k<<<64, 256>>>(r_out, 64, 16384, 16);
    bn_relu_k<<<EW, 256>>>(r_out, d3_g, d3_be);

    // output_map = conv7x7(r)
    conv7x7_k<<<dim3(8, 8, 16), dim3(16, 16)>>>(r_out, out_w, out_b, map_out);
}

// round 9
// speedup vs baseline: 3.5118x; 3.5118x over previous
#include <cuda_runtime.h>
#include <math.h>

// ---------------- scratch (no allocation allowed) ----------------
#define NEL 16777216  // 16*64*128*128  == 16*256*64*64
__device__ float g_buf0[NEL];
__device__ float g_buf1[NEL];
__device__ float g_buf2[NEL];
__device__ float g_imap[262144];   // 16*128*128
__device__ float g_inc[262144];
__device__ float g_mean[256];
__device__ float g_rstd[256];

// ============ 3x3 conv, pad=1, multi-output-channel blocked ============
// CTA: 256 threads; computes 32x32 spatial tile x 16 output channels.
// Thread (tx=tid&15, ty=tid>>4) owns 2x2 outputs per co -> acc[16][4].
// Optional fused BN+ReLU applied to the INPUT while loading (BNIN) —
// applied ONLY to in-bounds pixels; padding stays exactly 0.
// grid: (W/32, H/32, B * Cout/16)
template<int CIN, bool BNIN>
__global__ void __launch_bounds__(256, 2)
conv3x3mc(const float* __restrict__ in, const float* __restrict__ wt,
          const float* __restrict__ bias, float* __restrict__ out,
          const float* __restrict__ bng, const float* __restrict__ bnbe,
          int Cout, int H, int W) {
    constexpr int CICHUNK = 32;
    __shared__ __align__(16) float tile[2][34 * 36];
    __shared__ __align__(16) float wsm[CICHUNK * 16 * 12];
    const int tid = threadIdx.x;
    const int tx = tid & 15, ty = tid >> 4;
    const int groups = Cout >> 4;
    const int cog = blockIdx.z % groups;
    const int n   = blockIdx.z / groups;
    const int co0 = cog << 4;
    const int oy0 = blockIdx.y * 32, ox0 = blockIdx.x * 32;

    // precompute tile-load coords (no div/mod inside the ci loop)
    int soff[5], goff[5];
    bool gval[5], sval[5];
    #pragma unroll
    for (int k = 0; k < 5; k++) {
        int e = tid + k * 256;
        int ly = e / 34, lx = e - ly * 34;
        int gy = oy0 + ly - 1, gx = ox0 + lx - 1;
        sval[k] = (e < 34 * 34);
        gval[k] = sval[k] && gy >= 0 && gy < H && gx >= 0 && gx < W;
        soff[k] = ly * 36 + lx;
        goff[k] = gval[k] ? gy * W + gx : 0;
    }

    const float* inb = in + (size_t)n * CIN * H * W;

    // prologue: load ci=0 into tile[0] (BN only on in-bounds pixels)
    {
        float sc = 1.f, sh = 0.f;
        if (BNIN) { float s = g_rstd[0] * bng[0]; sc = s; sh = bnbe[0] - g_mean[0] * s; }
        #pragma unroll
        for (int k = 0; k < 5; k++) {
            float v = 0.f;
            if (gval[k]) {
                v = inb[goff[k]];
                if (BNIN) v = fmaxf(fmaf(v, sc, sh), 0.f);
            }
            if (sval[k]) tile[0][soff[k]] = v;
        }
    }

    float acc[16][4];
    #pragma unroll
    for (int c = 0; c < 16; c++)
        #pragma unroll
        for (int j = 0; j < 4; j++) acc[c][j] = 0.f;

    for (int ci = 0; ci < CIN; ci++) {
        const int cc = ci & (CICHUNK - 1);
        if (cc == 0) {
            __syncthreads();   // previous chunk's compute done before wsm overwrite
            #pragma unroll 2
            for (int i = tid; i < CICHUNK * 16 * 9; i += 256) {
                int c = i / 144; int r = i - c * 144; int co = r / 9; int j = r - co * 9;
                wsm[(c * 16 + co) * 12 + j] =
                    wt[(((size_t)(co0 + co)) * CIN + (ci + c)) * 9 + j];
            }
        }
        __syncthreads();       // tile[ci&1] stored & wsm ready; prev compute done
        const int buf = ci & 1;

        // prefetch next input channel into registers (overlaps compute)
        float pv[5];
        if (ci + 1 < CIN) {
            const float* ip = inb + (size_t)(ci + 1) * H * W;
            float sc = 1.f, sh = 0.f;
            if (BNIN) {
                float s = g_rstd[ci + 1] * bng[ci + 1];
                sc = s; sh = bnbe[ci + 1] - g_mean[ci + 1] * s;
            }
            #pragma unroll
            for (int k = 0; k < 5; k++) {
                float v = 0.f;
                if (gval[k]) {
                    v = ip[goff[k]];
                    if (BNIN) v = fmaxf(fmaf(v, sc, sh), 0.f);
                }
                pv[k] = v;
            }
        }

        // load this thread's 4x4 input patch
        float iv[4][4];
        #pragma unroll
        for (int r = 0; r < 4; r++) {
            const float* rp = &tile[buf][(ty * 2 + r) * 36 + tx * 2];
            float2 a = *(const float2*)rp;
            float2 b = *(const float2*)(rp + 2);
            iv[r][0] = a.x; iv[r][1] = a.y; iv[r][2] = b.x; iv[r][3] = b.y;
        }

        const float* wb = &wsm[cc * 192];
        #pragma unroll
        for (int co = 0; co < 16; co++) {
            float4 wa = *(const float4*)&wb[co * 12];
            float4 wc = *(const float4*)&wb[co * 12 + 4];
            float w8 = wb[co * 12 + 8];
            float w[9] = {wa.x, wa.y, wa.z, wa.w, wc.x, wc.y, wc.z, wc.w, w8};
            #pragma unroll
            for (int r2 = 0; r2 < 2; r2++)
                #pragma unroll
                for (int c2 = 0; c2 < 2; c2++) {
                    float s = acc[co][r2 * 2 + c2];
                    #pragma unroll
                    for (int dy = 0; dy < 3; dy++)
                        #pragma unroll
                        for (int dx = 0; dx < 3; dx++)
                            s = fmaf(iv[r2 + dy][c2 + dx], w[dy * 3 + dx], s);
                    acc[co][r2 * 2 + c2] = s;
                }
        }

        // commit prefetched tile
        if (ci + 1 < CIN) {
            #pragma unroll
            for (int k = 0; k < 5; k++)
                if (sval[k]) tile[buf ^ 1][soff[k]] = pv[k];
        }
    }

    // epilogue
    #pragma unroll
    for (int co = 0; co < 16; co++) {
        float bv = bias[co0 + co];
        size_t cb = ((size_t)n * Cout + co0 + co) * H * W;
        #pragma unroll
        for (int r2 = 0; r2 < 2; r2++) {
            int oy = oy0 + ty * 2 + r2;
            float2 o = make_float2(acc[co][r2 * 2] + bv, acc[co][r2 * 2 + 1] + bv);
            *(float2*)&out[cb + (size_t)oy * W + ox0 + tx * 2] = o;
        }
    }
}

// ---------------- BN batch statistics (one block per channel) ----------------
__global__ void bn_stats_k(const float* __restrict__ x, int C, int HW, int Bn) {
    const int c = blockIdx.x;
    const int N = Bn * HW;
    float s = 0.f, s2 = 0.f;
    for (int i = threadIdx.x; i < N; i += blockDim.x) {
        int n = i / HW, j = i - n * HW;
        float v = x[((size_t)n * C + c) * HW + j];
        s += v; s2 += v * v;
    }
    __shared__ float sh[256], sh2[256];
    sh[threadIdx.x] = s; sh2[threadIdx.x] = s2;
    __syncthreads();
    for (int o = 128; o > 0; o >>= 1) {
        if (threadIdx.x < o) { sh[threadIdx.x] += sh[threadIdx.x + o]; sh2[threadIdx.x] += sh2[threadIdx.x + o]; }
        __syncthreads();
    }
    if (threadIdx.x == 0) {
        float m = sh[0] / (float)N;
        float var = sh2[0] / (float)N - m * m;
        g_mean[c] = m;
        g_rstd[c] = rsqrtf(var + 1e-5f);
    }
}

// ---------------- BN apply + ReLU + PixelShuffle(2) ----------------
__global__ void bn_relu_ps_k(const float* __restrict__ y, const float* __restrict__ g,
                             const float* __restrict__ be, float* __restrict__ dep) {
    int idx = blockIdx.x * 256 + threadIdx.x;   // 0 .. 16M
    int X = idx & 127;
    int Y = (idx >> 7) & 127;
    int c = (idx >> 14) & 63;
    int n = idx >> 20;
    int cy = c * 4 + (Y & 1) * 2 + (X & 1);
    float v = y[(((size_t)n * 256 + cy) * 64 + (Y >> 1)) * 64 + (X >> 1)];
    v = (v - g_mean[cy]) * g_rstd[cy] * g[cy] + be[cy];
    dep[idx] = fmaxf(v, 0.f);
}

// ---------------- BN apply + ReLU (src -> dst) ----------------
__global__ void bn_relu_out_k(const float* __restrict__ x, const float* __restrict__ g,
                              const float* __restrict__ be, float* __restrict__ dst) {
    int idx = blockIdx.x * 256 + threadIdx.x;
    int c = (idx >> 14) & 63;    // HW = 16384, C = 64
    float v = x[idx];
    v = (v - g_mean[c]) * g_rstd[c] * g[c] + be[c];
    dst[idx] = fmaxf(v, 0.f);
}

// ---------------- bilinear x2 (align_corners) + sigmoid ----------------
__global__ void up_sig_k(const float* __restrict__ in) {
    int idx = blockIdx.x * 256 + threadIdx.x;   // 16*128*128
    int X = idx & 127, Y = (idx >> 7) & 127, n = idx >> 14;
    const float sc = 63.0f / 127.0f;
    float yy = Y * sc, xx = X * sc;
    int y0 = (int)floorf(yy); float wy = yy - (float)y0; int y1 = min(y0 + 1, 63);
    int x0 = (int)floorf(xx); float wx = xx - (float)x0; int x1 = min(x0 + 1, 63);
    const float* p = in + n * 4096;
    float r0 = p[y0 * 64 + x0] * (1.f - wx) + p[y0 * 64 + x1] * wx;
    float r1 = p[y1 * 64 + x0] * (1.f - wx) + p[y1 * 64 + x1] * wx;
    float v = r0 * (1.f - wy) + r1 * wy;
    g_imap[idx] = 1.f / (1.f + expf(-v));
}

// ---------------- increase_map = dilate3x3(imap) - imap ----------------
__global__ void inc_k() {
    int idx = blockIdx.x * 256 + threadIdx.x;   // 16*128*128
    int X = idx & 127, Y = (idx >> 7) & 127, n = idx >> 14;
    const float* p = g_imap + (n << 14);
    float m = -1e30f;
    #pragma unroll
    for (int dy = -1; dy <= 1; dy++) {
        int y = Y + dy;
        if (y < 0 || y > 127) continue;
        #pragma unroll
        for (int dx = -1; dx <= 1; dx++) {
            int x = X + dx;
            if (x < 0 || x > 127) continue;
            m = fmaxf(m, p[y * 128 + x]);
        }
    }
    g_inc[idx] = m - p[Y * 128 + X];
}

// ---------------- b_feature = cur_x * increase_map ----------------
__global__ void mult_k(const float* __restrict__ cur) {
    int idx = blockIdx.x * 256 + threadIdx.x;   // 16M
    int sp = idx & 16383;
    int n = idx >> 20;
    g_buf2[idx] = cur[idx] * g_inc[(n << 14) | sp];
}

// ---------------- t = dep + beta * fn ----------------
__global__ void add_k(const float* __restrict__ beta) {
    int idx = blockIdx.x * 256 + threadIdx.x;
    g_buf2[idx] = g_buf1[idx] + beta[0] * g_buf0[idx];
}

// ---------------- 7x7 conv, Cin=64 -> 1, pad=3 ----------------
__global__ void conv7x7_k(const float* __restrict__ in, const float* __restrict__ wt,
                          const float* __restrict__ bias, float* __restrict__ out) {
    __shared__ float tile[22][22];
    __shared__ float wsm[64 * 49];
    const int n = blockIdx.z;
    const int tid = threadIdx.y * 16 + threadIdx.x;
    for (int i = tid; i < 64 * 49; i += 256) wsm[i] = wt[i];
    const int oy0 = blockIdx.y * 16, ox0 = blockIdx.x * 16;
    float acc = 0.f;
    for (int ci = 0; ci < 64; ci++) {
        __syncthreads();
        const float* ip = in + ((size_t)n * 64 + ci) * 16384;
        for (int i = tid; i < 22 * 22; i += 256) {
            int ly = i / 22, lx = i % 22;
            int gy = oy0 + ly - 3, gx = ox0 + lx - 3;
            float v = 0.f;
            if (gy >= 0 && gy < 128 && gx >= 0 && gx < 128) v = ip[gy * 128 + gx];
            tile[ly][lx] = v;
        }
        __syncthreads();
        const float* wp = &wsm[ci * 49];
        #pragma unroll
        for (int dy = 0; dy < 7; dy++)
            #pragma unroll
            for (int dx = 0; dx < 7; dx++)
                acc = fmaf(tile[threadIdx.y + dy][threadIdx.x + dx], wp[dy * 7 + dx], acc);
    }
    out[((size_t)n * 128 + oy0 + threadIdx.y) * 128 + ox0 + threadIdx.x] = acc + bias[0];
}

// ---------------- launch ----------------
extern "C" void kernel_launch(void* const* d_in, const int* in_sizes, int n_in,
                              void* d_out, int out_size) {
    static float *buf0 = nullptr, *buf1 = nullptr, *buf2 = nullptr;
    if (!buf0) {
        cudaGetSymbolAddress((void**)&buf0, g_buf0);
        cudaGetSymbolAddress((void**)&buf1, g_buf1);
        cudaGetSymbolAddress((void**)&buf2, g_buf2);
    }
    const float* cur_x  = (const float*)d_in[0];
    const float* dep_x  = (const float*)d_in[1];
    const float* in_map = (const float*)d_in[2];
    const float* up_w   = (const float*)d_in[3];
    const float* up_b   = (const float*)d_in[4];
    const float* up_g   = (const float*)d_in[5];
    const float* up_be  = (const float*)d_in[6];
    const float* conv2_w = (const float*)d_in[7];
    const float* conv2_b = (const float*)d_in[8];
    const float* beta   = (const float*)d_in[9];
    const float* d1_w = (const float*)d_in[10], *d1_b = (const float*)d_in[11];
    const float* d1_g = (const float*)d_in[12], *d1_be = (const float*)d_in[13];
    const float* d2_w = (const float*)d_in[14], *d2_b = (const float*)d_in[15];
    const float* d2_g = (const float*)d_in[16], *d2_be = (const float*)d_in[17];
    const float* d3_w = (const float*)d_in[18], *d3_b = (const float*)d_in[19];
    const float* d3_g = (const float*)d_in[20], *d3_be = (const float*)d_in[21];
    const float* out_w = (const float*)d_in[22], *out_b = (const float*)d_in[23];

    float* r_out = (float*)d_out;               // [16,64,128,128]
    float* map_out = (float*)d_out + NEL;       // [16,1,128,128]

    dim3 gUp(2, 2, 16 * 16);      // 64x64, 32x32 tiles, Cout=256 -> 16 groups
    dim3 gD(4, 4, 16 * 4);        // 128x128, 32x32 tiles, Cout=64 -> 4 groups
    const int EW = NEL / 256;     // elementwise grid (65536)

    // up path: conv(C2->4C1) + BN + ReLU + pixel shuffle
    conv3x3mc<128, false><<<gUp, 256>>>(dep_x, up_w, up_b, buf0, nullptr, nullptr, 256, 64, 64);
    bn_stats_k<<<256, 256>>>(buf0, 256, 4096, 16);
    bn_relu_ps_k<<<EW, 256>>>(buf0, up_g, up_be, buf1);   // buf1 = dep

    // attention-map path
    up_sig_k<<<1024, 256>>>(in_map);
    inc_k<<<1024, 256>>>();
    mult_k<<<EW, 256>>>(cur_x);                            // buf2 = b_feature

    // fn = conv2(b_feature)
    conv3x3mc<64, false><<<gD, 256>>>(buf2, conv2_w, conv2_b, buf0, nullptr, nullptr, 64, 128, 128);
    add_k<<<EW, 256>>>(beta);                              // buf2 = dep + beta*fn

    // d1: conv(raw) -> buf0 ; stats on buf0
    conv3x3mc<64, false><<<gD, 256>>>(buf2, d1_w, d1_b, buf0, nullptr, nullptr, 64, 128, 128);
    bn_stats_k<<<64, 256>>>(buf0, 64, 16384, 16);
    // d2: conv with fused BN1+ReLU on input -> buf1 ; stats on buf1
    conv3x3mc<64, true><<<gD, 256>>>(buf0, d2_w, d2_b, buf1, d1_g, d1_be, 64, 128, 128);
    bn_stats_k<<<64, 256>>>(buf1, 64, 16384, 16);
    // d3: conv with fused BN2+ReLU on input -> buf2 ; stats on buf2
    conv3x3mc<64, true><<<gD, 256>>>(buf1, d3_w, d3_b, buf2, d2_g, d2_be, 64, 128, 128);
    bn_stats_k<<<64, 256>>>(buf2, 64, 16384, 16);
    // r = BN3 + ReLU -> output region
    bn_relu_out_k<<<EW, 256>>>(buf2, d3_g, d3_be, r_out);

    // output_map = conv7x7(r)
    conv7x7_k<<<dim3(8, 8, 16), dim3(16, 16)>>>(r_out, out_w, out_b, map_out);
}